// round 1
// baseline (speedup 1.0000x reference)
#include <cuda_runtime.h>
#include <cstdint>

#define NN 50000
#define NE 600000
#define NG 500
#define D 128
#define DOUT 32
#define NCHUNK 196  // ceil(NN/256)

// ---------------- scratch (static device globals; no allocation) ----------------
__device__ int   g_is64;
__device__ int   d_src[NE];
__device__ int   d_dst[NE];
__device__ float d_ew[NE];
__device__ float d_deg[NN];
__device__ float d_dinv[NN];
__device__ int   d_cnt[NN];
__device__ int   d_rowptr[NN + 1];
__device__ int   d_cursor[NN];
__device__ int   d_bsum[256];
__device__ int   d_boff[256];
__device__ int   d_csr_src[NE];
__device__ float d_csr_w[NE];
__device__ int   d_batch[NN];
__device__ float d_pool[NG * D];
__device__ int   d_gcnt[NG];
__device__ float d_buf0[(size_t)NN * D];
__device__ float d_buf1[(size_t)NN * D];
__device__ float d_buf2[(size_t)NN * D];

// ---------------- dtype detection (int64 vs int32 edge_index) ----------------
__global__ void detect_kernel(const int* __restrict__ ei_raw) {
    // If edge_index is int64 (values < 2^31, nonnegative), every odd int32 word is 0.
    // If int32, odd words are random node ids in [0, 50000): P(all 1024 == 0) ~ 0.
    int nz = 0;
    for (int i = threadIdx.x; i < 2048; i += 32)
        if (i & 1) nz += (ei_raw[i] != 0);
    for (int off = 16; off > 0; off >>= 1)
        nz += __shfl_down_sync(0xFFFFFFFFu, nz, off);
    if (threadIdx.x == 0) g_is64 = (nz == 0) ? 1 : 0;
}

// ---------------- zero scratch ----------------
__global__ void zero_kernel() {
    int i = blockIdx.x * blockDim.x + threadIdx.x;
    if (i < NN) { d_deg[i] = 0.0f; d_cnt[i] = 0; }
    if (i < NG * D) d_pool[i] = 0.0f;
    if (i < NG) d_gcnt[i] = 0;
}

// ---------------- convert edge_index/batch + out-degree histogram ----------------
__global__ void convert_kernel(const void* __restrict__ ei, const void* __restrict__ batch) {
    int e = blockIdx.x * blockDim.x + threadIdx.x;
    const bool is64 = (g_is64 != 0);
    if (e < NE) {
        int s, d;
        if (is64) {
            s = (int)((const long long*)ei)[e];
            d = (int)((const long long*)ei)[(size_t)NE + e];
        } else {
            s = ((const int*)ei)[e];
            d = ((const int*)ei)[NE + e];
        }
        d_src[e] = s;
        d_dst[e] = d;
        atomicAdd(&d_deg[s], 1.0f);
    }
    if (e < NN) {
        d_batch[e] = is64 ? (int)((const long long*)batch)[e] : ((const int*)batch)[e];
    }
}

__global__ void dinv_kernel() {
    int i = blockIdx.x * blockDim.x + threadIdx.x;
    if (i < NN) {
        float dg = d_deg[i];
        d_dinv[i] = (dg > 0.0f) ? rsqrtf(fmaxf(dg, 1.0f)) : 0.0f;
    }
}

// edge weights + in-degree (dst) histogram for CSR
__global__ void ew_hist_kernel() {
    int e = blockIdx.x * blockDim.x + threadIdx.x;
    if (e < NE) {
        int s = d_src[e], d = d_dst[e];
        d_ew[e] = -(d_dinv[s] * d_dinv[d]);
        atomicAdd(&d_cnt[d], 1);
    }
}

// ---------------- 3-pass exclusive scan of d_cnt -> d_rowptr ----------------
__global__ void scan1_kernel() {
    __shared__ int s[256];
    int tid = threadIdx.x;
    int i = blockIdx.x * 256 + tid;
    int v = (i < NN) ? d_cnt[i] : 0;
    s[tid] = v;
    __syncthreads();
    for (int off = 1; off < 256; off <<= 1) {
        int t = (tid >= off) ? s[tid - off] : 0;
        __syncthreads();
        s[tid] += t;
        __syncthreads();
    }
    int incl = s[tid];
    if (i < NN) d_rowptr[i] = incl - v;   // local exclusive
    if (tid == 255) d_bsum[blockIdx.x] = incl;
}

__global__ void scan2_kernel() {
    __shared__ int s[256];
    int tid = threadIdx.x;
    int v = (tid < NCHUNK) ? d_bsum[tid] : 0;
    s[tid] = v;
    __syncthreads();
    for (int off = 1; off < 256; off <<= 1) {
        int t = (tid >= off) ? s[tid - off] : 0;
        __syncthreads();
        s[tid] += t;
        __syncthreads();
    }
    d_boff[tid] = s[tid] - v;  // exclusive
}

__global__ void scan3_kernel() {
    int i = blockIdx.x * blockDim.x + threadIdx.x;
    if (i < NN) {
        int r = d_rowptr[i] + d_boff[i >> 8];
        d_rowptr[i] = r;
        d_cursor[i] = r;
    }
    if (i == NN) d_rowptr[NN] = NE;
}

__global__ void scatter_kernel() {
    int e = blockIdx.x * blockDim.x + threadIdx.x;
    if (e < NE) {
        int d = d_dst[e];
        int p = atomicAdd(&d_cursor[d], 1);
        d_csr_src[p] = d_src[e];
        d_csr_w[p] = d_ew[e];
    }
}

// ---------------- lhat: out[i,:] = sum_{e in CSR row i} w[e] * in[src[e],:] ----------------
__global__ void lhat_kernel(const float* __restrict__ in, float* __restrict__ out) {
    int w = (blockIdx.x * blockDim.x + threadIdx.x) >> 5;
    int lane = threadIdx.x & 31;
    if (w >= NN) return;
    int e = d_rowptr[w];
    const int e1 = d_rowptr[w + 1];
    float4 acc = make_float4(0.f, 0.f, 0.f, 0.f);
    const int q = lane * 4;
    for (; e + 2 <= e1; e += 2) {
        int s0 = d_csr_src[e];     float w0 = d_csr_w[e];
        int s1 = d_csr_src[e + 1]; float w1 = d_csr_w[e + 1];
        float4 v0 = *(const float4*)&in[(size_t)s0 * D + q];
        float4 v1 = *(const float4*)&in[(size_t)s1 * D + q];
        acc.x += w0 * v0.x + w1 * v1.x;
        acc.y += w0 * v0.y + w1 * v1.y;
        acc.z += w0 * v0.z + w1 * v1.z;
        acc.w += w0 * v0.w + w1 * v1.w;
    }
    if (e < e1) {
        int s0 = d_csr_src[e]; float w0 = d_csr_w[e];
        float4 v0 = *(const float4*)&in[(size_t)s0 * D + q];
        acc.x += w0 * v0.x; acc.y += w0 * v0.y;
        acc.z += w0 * v0.z; acc.w += w0 * v0.w;
    }
    *(float4*)&out[(size_t)w * D + q] = acc;
}

// ---------------- T2 = 2*T2 - X0 (elementwise) ----------------
__global__ void combine_kernel(float4* __restrict__ T2, const float4* __restrict__ X0) {
    int i = blockIdx.x * blockDim.x + threadIdx.x;
    if (i < NN * D / 4) {
        float4 t = T2[i];
        float4 x = X0[i];
        t.x = 2.f * t.x - x.x; t.y = 2.f * t.y - x.y;
        t.z = 2.f * t.z - x.z; t.w = 2.f * t.w - x.w;
        T2[i] = t;
    }
}

// ---------------- Out = relu(X0@W0 + X1@W1 + X2@W2 + b); Out may alias X2 ----------------
// BM=64, BN=128, KC=16, 256 threads, thread tile 4x8.
__global__ void __launch_bounds__(256) gemm3_kernel(
    const float* __restrict__ X0, const float* __restrict__ X1,
    const float* __restrict__ X2, const float* __restrict__ W,
    const float* __restrict__ bias, float* __restrict__ Out)
{
    __shared__ float As[16][64];
    __shared__ float Bs[16][128];
    const int tid = threadIdx.x;
    const int m0 = blockIdx.x * 64;
    const int tc = tid & 15;   // col group: cols tc*8 .. tc*8+7
    const int tr = tid >> 4;   // row group: rows tr*4 .. tr*4+3

    float acc[4][8];
#pragma unroll
    for (int r = 0; r < 4; ++r)
#pragma unroll
        for (int c = 0; c < 8; ++c) acc[r][c] = 0.f;

    float bs[8];
#pragma unroll
    for (int c = 0; c < 8; ++c) bs[c] = bias[tc * 8 + c];

    const int arow = tid >> 2;          // 0..63
    const int acg  = (tid & 3) * 4;     // 0,4,8,12

#pragma unroll
    for (int sel = 0; sel < 3; ++sel) {
        const float* X  = (sel == 0) ? X0 : (sel == 1) ? X1 : X2;
        const float* Wk = W + sel * (D * D);
        for (int kb = 0; kb < 8; ++kb) {
            const int kc0 = kb * 16;
            // load A tile (transposed into smem)
            {
                int m = m0 + arow;
                float4 v = make_float4(0.f, 0.f, 0.f, 0.f);
                if (m < NN) v = *(const float4*)&X[(size_t)m * D + kc0 + acg];
                As[acg + 0][arow] = v.x;
                As[acg + 1][arow] = v.y;
                As[acg + 2][arow] = v.z;
                As[acg + 3][arow] = v.w;
            }
            // load B tile
#pragma unroll
            for (int j = 0; j < 2; ++j) {
                int lin = tid + j * 256;        // 0..511
                int row = lin >> 5;             // 0..15
                int cg  = (lin & 31) * 4;       // 0..124
                *(float4*)&Bs[row][cg] = *(const float4*)&Wk[(kc0 + row) * D + cg];
            }
            __syncthreads();
#pragma unroll
            for (int kk = 0; kk < 16; ++kk) {
                float4 a  = *(const float4*)&As[kk][tr * 4];
                float4 b0 = *(const float4*)&Bs[kk][tc * 8];
                float4 b1 = *(const float4*)&Bs[kk][tc * 8 + 4];
                float av[4] = {a.x, a.y, a.z, a.w};
                float bv[8] = {b0.x, b0.y, b0.z, b0.w, b1.x, b1.y, b1.z, b1.w};
#pragma unroll
                for (int r = 0; r < 4; ++r)
#pragma unroll
                    for (int c = 0; c < 8; ++c)
                        acc[r][c] += av[r] * bv[c];
            }
            __syncthreads();
        }
    }

#pragma unroll
    for (int r = 0; r < 4; ++r) {
        int m = m0 + tr * 4 + r;
        if (m < NN) {
            float4 o0, o1;
            o0.x = fmaxf(acc[r][0] + bs[0], 0.f);
            o0.y = fmaxf(acc[r][1] + bs[1], 0.f);
            o0.z = fmaxf(acc[r][2] + bs[2], 0.f);
            o0.w = fmaxf(acc[r][3] + bs[3], 0.f);
            o1.x = fmaxf(acc[r][4] + bs[4], 0.f);
            o1.y = fmaxf(acc[r][5] + bs[5], 0.f);
            o1.z = fmaxf(acc[r][6] + bs[6], 0.f);
            o1.w = fmaxf(acc[r][7] + bs[7], 0.f);
            float* o = &Out[(size_t)m * D + tc * 8];
            *(float4*)o = o0;
            *(float4*)(o + 4) = o1;
        }
    }
}

// ---------------- pooling: atomic sum per graph + node counts ----------------
__global__ void pool_kernel(const float* __restrict__ H) {
    int idx = blockIdx.x * blockDim.x + threadIdx.x;
    int node = idx >> 5;
    int q = idx & 31;
    if (node < NN) {
        int b = d_batch[node];
        float4 v = *(const float4*)&H[(size_t)node * D + q * 4];
        atomicAdd(&d_pool[b * D + q * 4 + 0], v.x);
        atomicAdd(&d_pool[b * D + q * 4 + 1], v.y);
        atomicAdd(&d_pool[b * D + q * 4 + 2], v.z);
        atomicAdd(&d_pool[b * D + q * 4 + 3], v.w);
        if (q == 0) atomicAdd(&d_gcnt[b], 1);
    }
}

// ---------------- final: out[g,:] = (pool[g,:]/max(cnt,1)) @ Wout + bout ----------------
__global__ void final_kernel(const float* __restrict__ Wout, const float* __restrict__ bout,
                             float* __restrict__ out) {
    int g = blockIdx.x;
    int t = threadIdx.x;  // 32
    float cnt = (float)d_gcnt[g];
    float s = 1.0f / fmaxf(cnt, 1.0f);
    const float* p = &d_pool[g * D];
    float acc = 0.f;
#pragma unroll 8
    for (int i = 0; i < D; ++i) acc += p[i] * Wout[i * DOUT + t];
    out[g * DOUT + t] = bout[t] + s * acc;
}

// ---------------- launch ----------------
extern "C" void kernel_launch(void* const* d_in, const int* in_sizes, int n_in,
                              void* d_out, int out_size) {
    const float* x    = (const float*)d_in[0];
    const void*  ei   = d_in[1];
    const void*  batch = d_in[2];
    const float* W1   = (const float*)d_in[3];
    const float* b1   = (const float*)d_in[4];
    const float* W2   = (const float*)d_in[5];
    const float* b2   = (const float*)d_in[6];
    const float* W3   = (const float*)d_in[7];
    const float* b3   = (const float*)d_in[8];
    const float* Wout = (const float*)d_in[9];
    const float* bout = (const float*)d_in[10];
    float* out = (float*)d_out;

    float *B0, *B1, *B2;
    cudaGetSymbolAddress((void**)&B0, d_buf0);
    cudaGetSymbolAddress((void**)&B1, d_buf1);
    cudaGetSymbolAddress((void**)&B2, d_buf2);

    const int T = 256;
    const int gE = (NE + T - 1) / T;          // 2344
    const int gN = (NN + T - 1) / T;          // 196
    const int gN1 = (NN + 1 + T - 1) / T;     // 196
    const int gW = (NN * 32 + T - 1) / T;     // warp-per-node grids: 6250
    const int gC = (NN * D / 4 + T - 1) / T;  // 6250
    const int gM = (NN + 63) / 64;            // 782

    detect_kernel<<<1, 32>>>((const int*)ei);
    zero_kernel<<<(NG * D + T - 1) / T > gN ? (NG * D + T - 1) / T : gN, T>>>();
    convert_kernel<<<gE, T>>>(ei, batch);
    dinv_kernel<<<gN, T>>>();
    ew_hist_kernel<<<gE, T>>>();
    scan1_kernel<<<NCHUNK, 256>>>();
    scan2_kernel<<<1, 256>>>();
    scan3_kernel<<<gN1, T>>>();
    scatter_kernel<<<gE, T>>>();

    // Layer 1: in = x
    lhat_kernel<<<gW, T>>>(x, B0);
    lhat_kernel<<<gW, T>>>(B0, B1);
    combine_kernel<<<gC, T>>>((float4*)B1, (const float4*)x);
    gemm3_kernel<<<gM, 256>>>(x, B0, B1, W1, b1, B1);

    // Layer 2: in = B1
    lhat_kernel<<<gW, T>>>(B1, B0);
    lhat_kernel<<<gW, T>>>(B0, B2);
    combine_kernel<<<gC, T>>>((float4*)B2, (const float4*)B1);
    gemm3_kernel<<<gM, 256>>>(B1, B0, B2, W2, b2, B2);

    // Layer 3: in = B2
    lhat_kernel<<<gW, T>>>(B2, B0);
    lhat_kernel<<<gW, T>>>(B0, B1);
    combine_kernel<<<gC, T>>>((float4*)B1, (const float4*)B2);
    gemm3_kernel<<<gM, 256>>>(B2, B0, B1, W3, b3, B1);

    // Pool + final projection
    pool_kernel<<<gW, T>>>(B1);
    final_kernel<<<NG, 32>>>(Wout, bout, out);
}

// round 2
// speedup vs baseline: 1.9779x; 1.9779x over previous
#include <cuda_runtime.h>
#include <cuda_bf16.h>
#include <cstdint>

#define NN 50000
#define NE 600000
#define NG 500
#define D 128
#define DOUT 32
#define NCHUNK 196  // ceil(NN/256)
#define WSZ (3*128*128)  // 49152 weights per layer

// ---------------- scratch (static device globals; no allocation) ----------------
__device__ int   g_is64;
__device__ int   d_src[NE];
__device__ int   d_dst[NE];
__device__ float d_ew[NE];
__device__ float d_deg[NN];
__device__ float d_dinv[NN];
__device__ int   d_cnt[NN];
__device__ int   d_rowptr[NN + 1];
__device__ int   d_cursor[NN];
__device__ int   d_bsum[256];
__device__ int   d_boff[256];
__device__ int   d_csr_src[NE];
__device__ float d_csr_w[NE];
__device__ int   d_batch[NN];
__device__ int   d_gstart[NG + 1];
__device__ float d_pool[NG * D];
__device__ float d_buf0[(size_t)NN * D];
__device__ float d_buf1[(size_t)NN * D];
__device__ float d_buf2[(size_t)NN * D];
__device__ __nv_bfloat16 d_Whi[3 * WSZ];
__device__ __nv_bfloat16 d_Wlo[3 * WSZ];

// ---------------- dtype detection (int64 vs int32 edge_index) ----------------
__global__ void detect_kernel(const int* __restrict__ ei_raw) {
    int nz = 0;
    for (int i = threadIdx.x; i < 2048; i += 32)
        if (i & 1) nz += (ei_raw[i] != 0);
    for (int off = 16; off > 0; off >>= 1)
        nz += __shfl_down_sync(0xFFFFFFFFu, nz, off);
    if (threadIdx.x == 0) g_is64 = (nz == 0) ? 1 : 0;
}

__global__ void zero_kernel() {
    int i = blockIdx.x * blockDim.x + threadIdx.x;
    if (i < NN) { d_deg[i] = 0.0f; d_cnt[i] = 0; }
}

__global__ void convert_kernel(const void* __restrict__ ei, const void* __restrict__ batch) {
    int e = blockIdx.x * blockDim.x + threadIdx.x;
    const bool is64 = (g_is64 != 0);
    if (e < NE) {
        int s, d;
        if (is64) {
            s = (int)((const long long*)ei)[e];
            d = (int)((const long long*)ei)[(size_t)NE + e];
        } else {
            s = ((const int*)ei)[e];
            d = ((const int*)ei)[NE + e];
        }
        d_src[e] = s;
        d_dst[e] = d;
        atomicAdd(&d_deg[s], 1.0f);
    }
    if (e < NN) {
        d_batch[e] = is64 ? (int)((const long long*)batch)[e] : ((const int*)batch)[e];
    }
}

__global__ void dinv_kernel() {
    int i = blockIdx.x * blockDim.x + threadIdx.x;
    if (i < NN) {
        float dg = d_deg[i];
        d_dinv[i] = (dg > 0.0f) ? rsqrtf(fmaxf(dg, 1.0f)) : 0.0f;
    }
}

__global__ void ew_hist_kernel() {
    int e = blockIdx.x * blockDim.x + threadIdx.x;
    if (e < NE) {
        int s = d_src[e], d = d_dst[e];
        d_ew[e] = -(d_dinv[s] * d_dinv[d]);
        atomicAdd(&d_cnt[d], 1);
    }
}

// ---------------- 3-pass exclusive scan ----------------
__global__ void scan1_kernel() {
    __shared__ int s[256];
    int tid = threadIdx.x;
    int i = blockIdx.x * 256 + tid;
    int v = (i < NN) ? d_cnt[i] : 0;
    s[tid] = v;
    __syncthreads();
    for (int off = 1; off < 256; off <<= 1) {
        int t = (tid >= off) ? s[tid - off] : 0;
        __syncthreads();
        s[tid] += t;
        __syncthreads();
    }
    int incl = s[tid];
    if (i < NN) d_rowptr[i] = incl - v;
    if (tid == 255) d_bsum[blockIdx.x] = incl;
}

__global__ void scan2_kernel() {
    __shared__ int s[256];
    int tid = threadIdx.x;
    int v = (tid < NCHUNK) ? d_bsum[tid] : 0;
    s[tid] = v;
    __syncthreads();
    for (int off = 1; off < 256; off <<= 1) {
        int t = (tid >= off) ? s[tid - off] : 0;
        __syncthreads();
        s[tid] += t;
        __syncthreads();
    }
    d_boff[tid] = s[tid] - v;
}

__global__ void scan3_kernel() {
    int i = blockIdx.x * blockDim.x + threadIdx.x;
    if (i < NN) {
        int r = d_rowptr[i] + d_boff[i >> 8];
        d_rowptr[i] = r;
        d_cursor[i] = r;
    }
    if (i == NN) d_rowptr[NN] = NE;
}

__global__ void scatter_kernel() {
    int e = blockIdx.x * blockDim.x + threadIdx.x;
    if (e < NE) {
        int d = d_dst[e];
        int p = atomicAdd(&d_cursor[d], 1);
        d_csr_src[p] = d_src[e];
        d_csr_w[p] = d_ew[e];
    }
}

// ---------------- weight preconvert: fp32 -> bf16 hi/lo ----------------
__global__ void wconv_kernel(const float* __restrict__ W1, const float* __restrict__ W2,
                             const float* __restrict__ W3) {
    int i = blockIdx.x * blockDim.x + threadIdx.x;
    if (i >= 3 * WSZ) return;
    const float* W = (i < WSZ) ? W1 : (i < 2 * WSZ) ? W2 : W3;
    float v = W[i % WSZ];
    __nv_bfloat16 h = __float2bfloat16(v);
    float r = v - __bfloat162float(h);
    d_Whi[i] = h;
    d_Wlo[i] = __float2bfloat16(r);
}

// ---------------- lhat ----------------
__global__ void lhat_kernel(const float* __restrict__ in, float* __restrict__ out) {
    int w = (blockIdx.x * blockDim.x + threadIdx.x) >> 5;
    int lane = threadIdx.x & 31;
    if (w >= NN) return;
    int e = d_rowptr[w];
    const int e1 = d_rowptr[w + 1];
    float4 acc = make_float4(0.f, 0.f, 0.f, 0.f);
    const int q = lane * 4;
    for (; e + 4 <= e1; e += 4) {
        int s0 = d_csr_src[e];     float w0 = d_csr_w[e];
        int s1 = d_csr_src[e + 1]; float w1 = d_csr_w[e + 1];
        int s2 = d_csr_src[e + 2]; float w2 = d_csr_w[e + 2];
        int s3 = d_csr_src[e + 3]; float w3 = d_csr_w[e + 3];
        float4 v0 = *(const float4*)&in[(size_t)s0 * D + q];
        float4 v1 = *(const float4*)&in[(size_t)s1 * D + q];
        float4 v2 = *(const float4*)&in[(size_t)s2 * D + q];
        float4 v3 = *(const float4*)&in[(size_t)s3 * D + q];
        acc.x += w0 * v0.x + w1 * v1.x + w2 * v2.x + w3 * v3.x;
        acc.y += w0 * v0.y + w1 * v1.y + w2 * v2.y + w3 * v3.y;
        acc.z += w0 * v0.z + w1 * v1.z + w2 * v2.z + w3 * v3.z;
        acc.w += w0 * v0.w + w1 * v1.w + w2 * v2.w + w3 * v3.w;
    }
    for (; e < e1; ++e) {
        int s0 = d_csr_src[e]; float w0 = d_csr_w[e];
        float4 v0 = *(const float4*)&in[(size_t)s0 * D + q];
        acc.x += w0 * v0.x; acc.y += w0 * v0.y;
        acc.z += w0 * v0.z; acc.w += w0 * v0.w;
    }
    *(float4*)&out[(size_t)w * D + q] = acc;
}

// ---------------- tensor-core gemm3 helpers ----------------
__device__ __forceinline__ void ldsm4(uint32_t a, uint32_t& r0, uint32_t& r1,
                                      uint32_t& r2, uint32_t& r3) {
    asm volatile("ldmatrix.sync.aligned.m8n8.x4.shared.b16 {%0,%1,%2,%3}, [%4];"
                 : "=r"(r0), "=r"(r1), "=r"(r2), "=r"(r3) : "r"(a));
}
__device__ __forceinline__ void ldsm4t(uint32_t a, uint32_t& r0, uint32_t& r1,
                                       uint32_t& r2, uint32_t& r3) {
    asm volatile("ldmatrix.sync.aligned.m8n8.x4.trans.shared.b16 {%0,%1,%2,%3}, [%4];"
                 : "=r"(r0), "=r"(r1), "=r"(r2), "=r"(r3) : "r"(a));
}
__device__ __forceinline__ void mma16816(float* c, const uint32_t* a, const uint32_t* b) {
    asm volatile(
        "mma.sync.aligned.m16n8k16.row.col.f32.bf16.bf16.f32 "
        "{%0,%1,%2,%3}, {%4,%5,%6,%7}, {%8,%9}, {%0,%1,%2,%3};"
        : "+f"(c[0]), "+f"(c[1]), "+f"(c[2]), "+f"(c[3])
        : "r"(a[0]), "r"(a[1]), "r"(a[2]), "r"(a[3]), "r"(b[0]), "r"(b[1]));
}
__device__ __forceinline__ uint32_t packbf(__nv_bfloat16 a, __nv_bfloat16 b) {
    return (uint32_t)__bfloat16_as_ushort(a) | ((uint32_t)__bfloat16_as_ushort(b) << 16);
}
__device__ __forceinline__ void cvt_hilo4(float4 v, uint2& hi, uint2& lo) {
    __nv_bfloat16 h0 = __float2bfloat16(v.x), h1 = __float2bfloat16(v.y);
    __nv_bfloat16 h2 = __float2bfloat16(v.z), h3 = __float2bfloat16(v.w);
    __nv_bfloat16 l0 = __float2bfloat16(v.x - __bfloat162float(h0));
    __nv_bfloat16 l1 = __float2bfloat16(v.y - __bfloat162float(h1));
    __nv_bfloat16 l2 = __float2bfloat16(v.z - __bfloat162float(h2));
    __nv_bfloat16 l3 = __float2bfloat16(v.w - __bfloat162float(h3));
    hi = make_uint2(packbf(h0, h1), packbf(h2, h3));
    lo = make_uint2(packbf(l0, l1), packbf(l2, l3));
}

// ---------------- Out = relu(X0@W0 + X1@W1 + (2*X2-X0)@W2 + b) ----------------
// BM=128, N=128 (full), K chunks of 16. 256 threads = 8 warps, warp tile 64x32.
// bf16 hi/lo split, 3-product compensation => ~fp32 accuracy on tensor cores.
__global__ void __launch_bounds__(256) gemm3_kernel(
    const float* __restrict__ X0, const float* __restrict__ X1,
    const float* __restrict__ X2, const __nv_bfloat16* __restrict__ Whi,
    const __nv_bfloat16* __restrict__ Wlo, const float* __restrict__ bias,
    float* __restrict__ Out)
{
    __shared__ __align__(16) unsigned char sA_hi[128 * 48];   // 128 rows, 16 bf16 + pad to 48B
    __shared__ __align__(16) unsigned char sA_lo[128 * 48];
    __shared__ __align__(16) unsigned char sB_hi[16 * 272];   // 16 k-rows, 128 bf16 + pad to 272B
    __shared__ __align__(16) unsigned char sB_lo[16 * 272];
    __shared__ float s_bias[128];

    const int tid = threadIdx.x;
    const int lane = tid & 31;
    const int wid = tid >> 5;
    const int wr = wid >> 2;   // 0..1
    const int wc = wid & 3;    // 0..3
    const int m0 = blockIdx.x * 128;

    if (tid < 128) s_bias[tid] = bias[tid];

    float acc[4][4][4];
#pragma unroll
    for (int f = 0; f < 4; ++f)
#pragma unroll
        for (int t = 0; t < 4; ++t)
#pragma unroll
            for (int i = 0; i < 4; ++i) acc[f][t][i] = 0.f;

    const uint32_t sAhiB = (uint32_t)__cvta_generic_to_shared(sA_hi);
    const uint32_t sAloB = (uint32_t)__cvta_generic_to_shared(sA_lo);
    const uint32_t sBhiB = (uint32_t)__cvta_generic_to_shared(sB_hi);
    const uint32_t sBloB = (uint32_t)__cvta_generic_to_shared(sB_lo);

    const uint32_t aoff = (uint32_t)(lane & 15) * 48 + (uint32_t)(lane >> 4) * 16;
    const uint32_t boff = (uint32_t)(lane & 15) * 272 + (uint32_t)((lane >> 4) * 8) * 2;

    for (int sel = 0; sel < 3; ++sel) {
        const float* X = (sel == 0) ? X0 : (sel == 1) ? X1 : X2;
        const __nv_bfloat16* WH = Whi + sel * (D * D);
        const __nv_bfloat16* WL = Wlo + sel * (D * D);
        for (int kb = 0; kb < 8; ++kb) {
            const int kc0 = kb * 16;
            // ---- stage A chunk (128x16 fp32 -> bf16 hi/lo) ----
#pragma unroll
            for (int j = 0; j < 2; ++j) {
                int id = tid + j * 256;
                int row = id >> 2, cg = id & 3;
                int m = m0 + row;
                float4 v = make_float4(0.f, 0.f, 0.f, 0.f);
                if (m < NN) {
                    v = *(const float4*)&X[(size_t)m * D + kc0 + cg * 4];
                    if (sel == 2) {
                        float4 u = *(const float4*)&X0[(size_t)m * D + kc0 + cg * 4];
                        v.x = 2.f * v.x - u.x; v.y = 2.f * v.y - u.y;
                        v.z = 2.f * v.z - u.z; v.w = 2.f * v.w - u.w;
                    }
                }
                uint2 hi, lo;
                cvt_hilo4(v, hi, lo);
                *(uint2*)(sA_hi + row * 48 + cg * 8) = hi;
                *(uint2*)(sA_lo + row * 48 + cg * 8) = lo;
            }
            // ---- stage B chunk (16x128 bf16, preconverted) ----
            {
                int row = tid >> 4, c8 = (tid & 15) * 8;
                *(uint4*)(sB_hi + row * 272 + c8 * 2) =
                    *(const uint4*)(WH + (kc0 + row) * D + c8);
                *(uint4*)(sB_lo + row * 272 + c8 * 2) =
                    *(const uint4*)(WL + (kc0 + row) * D + c8);
            }
            __syncthreads();

            // ---- fragments ----
            uint32_t ahi[4][4], alo[4][4], bhi[4][2], blo[4][2];
#pragma unroll
            for (int f = 0; f < 4; ++f) {
                uint32_t rb = (uint32_t)(wr * 64 + f * 16) * 48 + aoff;
                ldsm4(sAhiB + rb, ahi[f][0], ahi[f][1], ahi[f][2], ahi[f][3]);
                ldsm4(sAloB + rb, alo[f][0], alo[f][1], alo[f][2], alo[f][3]);
            }
#pragma unroll
            for (int nb = 0; nb < 2; ++nb) {
                uint32_t cb = boff + (uint32_t)(wc * 32 + nb * 16) * 2;
                uint32_t r0, r1, r2, r3;
                ldsm4t(sBhiB + cb, r0, r1, r2, r3);
                bhi[nb * 2][0] = r0; bhi[nb * 2][1] = r1;
                bhi[nb * 2 + 1][0] = r2; bhi[nb * 2 + 1][1] = r3;
                ldsm4t(sBloB + cb, r0, r1, r2, r3);
                blo[nb * 2][0] = r0; blo[nb * 2][1] = r1;
                blo[nb * 2 + 1][0] = r2; blo[nb * 2 + 1][1] = r3;
            }
            // ---- compute: hi*hi + hi*lo + lo*hi ----
#pragma unroll
            for (int f = 0; f < 4; ++f)
#pragma unroll
                for (int t = 0; t < 4; ++t) {
                    mma16816(acc[f][t], ahi[f], bhi[t]);
                    mma16816(acc[f][t], ahi[f], blo[t]);
                    mma16816(acc[f][t], alo[f], bhi[t]);
                }
            __syncthreads();
        }
    }

    // ---- epilogue: bias + relu ----
#pragma unroll
    for (int f = 0; f < 4; ++f) {
        int r0 = m0 + wr * 64 + f * 16 + (lane >> 2);
        int r1 = r0 + 8;
#pragma unroll
        for (int t = 0; t < 4; ++t) {
            int cb = wc * 32 + t * 8 + (lane & 3) * 2;
            if (r0 < NN) {
                float2 o;
                o.x = fmaxf(acc[f][t][0] + s_bias[cb], 0.f);
                o.y = fmaxf(acc[f][t][1] + s_bias[cb + 1], 0.f);
                *(float2*)&Out[(size_t)r0 * D + cb] = o;
            }
            if (r1 < NN) {
                float2 o;
                o.x = fmaxf(acc[f][t][2] + s_bias[cb], 0.f);
                o.y = fmaxf(acc[f][t][3] + s_bias[cb + 1], 0.f);
                *(float2*)&Out[(size_t)r1 * D + cb] = o;
            }
        }
    }
}

// ---------------- pooling via sorted-batch boundaries (no atomics) ----------------
__global__ void bounds_kernel() {
    int g = blockIdx.x * blockDim.x + threadIdx.x;
    if (g > NG) return;
    int lo = 0, hi = NN;
    while (lo < hi) {
        int mid = (lo + hi) >> 1;
        if (d_batch[mid] < g) lo = mid + 1; else hi = mid;
    }
    d_gstart[g] = lo;
}

__global__ void pool2_kernel(const float* __restrict__ H) {
    int g = blockIdx.x;
    int t = threadIdx.x;  // 128
    int s = d_gstart[g], e = d_gstart[g + 1];
    float acc = 0.f;
#pragma unroll 4
    for (int n = s; n < e; ++n) acc += H[(size_t)n * D + t];
    d_pool[g * D + t] = acc / fmaxf((float)(e - s), 1.0f);
}

__global__ void final_kernel(const float* __restrict__ Wout, const float* __restrict__ bout,
                             float* __restrict__ out) {
    int g = blockIdx.x;
    int t = threadIdx.x;  // 32
    const float* p = &d_pool[g * D];
    float acc = 0.f;
#pragma unroll 8
    for (int i = 0; i < D; ++i) acc += p[i] * Wout[i * DOUT + t];
    out[g * DOUT + t] = bout[t] + acc;
}

// ---------------- launch ----------------
extern "C" void kernel_launch(void* const* d_in, const int* in_sizes, int n_in,
                              void* d_out, int out_size) {
    const float* x     = (const float*)d_in[0];
    const void*  ei    = d_in[1];
    const void*  batch = d_in[2];
    const float* W1    = (const float*)d_in[3];
    const float* b1    = (const float*)d_in[4];
    const float* W2    = (const float*)d_in[5];
    const float* b2    = (const float*)d_in[6];
    const float* W3    = (const float*)d_in[7];
    const float* b3    = (const float*)d_in[8];
    const float* Wout  = (const float*)d_in[9];
    const float* bout  = (const float*)d_in[10];
    float* out = (float*)d_out;

    float *B0, *B1, *B2;
    __nv_bfloat16 *Whi, *Wlo;
    cudaGetSymbolAddress((void**)&B0, d_buf0);
    cudaGetSymbolAddress((void**)&B1, d_buf1);
    cudaGetSymbolAddress((void**)&B2, d_buf2);
    cudaGetSymbolAddress((void**)&Whi, d_Whi);
    cudaGetSymbolAddress((void**)&Wlo, d_Wlo);

    const int T = 256;
    const int gE = (NE + T - 1) / T;
    const int gN = (NN + T - 1) / T;
    const int gW = (NN * 32 + T - 1) / T;
    const int gM = (NN + 127) / 128;        // 391
    const int gWc = (3 * WSZ + T - 1) / T;

    detect_kernel<<<1, 32>>>((const int*)ei);
    zero_kernel<<<gN, T>>>();
    convert_kernel<<<gE, T>>>(ei, batch);
    dinv_kernel<<<gN, T>>>();
    ew_hist_kernel<<<gE, T>>>();
    scan1_kernel<<<NCHUNK, 256>>>();
    scan2_kernel<<<1, 256>>>();
    scan3_kernel<<<gN, T>>>();
    scatter_kernel<<<gE, T>>>();
    wconv_kernel<<<gWc, T>>>(W1, W2, W3);

    // Layer 1
    lhat_kernel<<<gW, T>>>(x, B0);
    lhat_kernel<<<gW, T>>>(B0, B1);
    gemm3_kernel<<<gM, 256>>>(x, B0, B1, Whi, Wlo, b1, B1);

    // Layer 2
    lhat_kernel<<<gW, T>>>(B1, B0);
    lhat_kernel<<<gW, T>>>(B0, B2);
    gemm3_kernel<<<gM, 256>>>(B1, B0, B2, Whi + WSZ, Wlo + WSZ, b2, B2);

    // Layer 3
    lhat_kernel<<<gW, T>>>(B2, B0);
    lhat_kernel<<<gW, T>>>(B0, B1);
    gemm3_kernel<<<gM, 256>>>(B2, B0, B1, Whi + 2 * WSZ, Wlo + 2 * WSZ, b3, B1);

    // Pool + final
    bounds_kernel<<<2, 256>>>();
    pool2_kernel<<<NG, 128>>>(B1);
    final_kernel<<<NG, 32>>>(Wout, bout, out);
}

// round 3
// speedup vs baseline: 2.1657x; 1.0949x over previous
#include <cuda_runtime.h>
#include <cuda_bf16.h>
#include <cuda_fp16.h>
#include <cstdint>

#define NN 50000
#define NE 600000
#define NG 500
#define D 128
#define DOUT 32
#define NCHUNK 196       // ceil(NN/256)
#define WTERM 16384      // 128*128
#define WSZ (3*WTERM)    // per-layer folded terms

// ---------------- scratch ----------------
__device__ int   g_is64;
__device__ int   d_src[NE];
__device__ int   d_dst[NE];
__device__ int   d_degi[NN];
__device__ float d_dinv[NN];
__device__ int   d_cnt[NN];
__device__ int   d_rowptr[NN + 1];
__device__ int   d_cursor[NN];
__device__ int   d_bsum[256];
__device__ int   d_boff[256];
__device__ int   d_csr_src[NE];
__device__ float d_csr_w[NE];
__device__ int   d_batch[NN];
__device__ float d_buf0[(size_t)NN * D];
__device__ float d_buf1[(size_t)NN * D];
__device__ float d_buf2[(size_t)NN * D];
__device__ uint2 d_h16a[(size_t)NN * 32];   // fp16 copy of layer input X
__device__ uint2 d_h16b[(size_t)NN * 32];   // fp16 copy of Tx1
__device__ __nv_bfloat16 d_Whi[3 * WSZ];
__device__ __nv_bfloat16 d_Wlo[3 * WSZ];

// ---------------- zero + dtype detect ----------------
__global__ void zero_kernel(const int* __restrict__ ei_raw) {
    int i = blockIdx.x * blockDim.x + threadIdx.x;
    if (i < NN) { d_degi[i] = 0; d_cnt[i] = 0; }
    if (blockIdx.x == 0 && threadIdx.x < 32) {
        int nz = 0;
        for (int j = threadIdx.x; j < 2048; j += 32)
            if (j & 1) nz += (ei_raw[j] != 0);
        for (int off = 16; off > 0; off >>= 1)
            nz += __shfl_down_sync(0xFFFFFFFFu, nz, off);
        if (threadIdx.x == 0) g_is64 = (nz == 0) ? 1 : 0;
    }
}

// ---------------- convert + both degree histograms ----------------
__global__ void convert_kernel(const void* __restrict__ ei, const void* __restrict__ batch) {
    int e = blockIdx.x * blockDim.x + threadIdx.x;
    const bool is64 = (g_is64 != 0);
    if (e < NE) {
        int s, d;
        if (is64) {
            s = (int)((const long long*)ei)[e];
            d = (int)((const long long*)ei)[(size_t)NE + e];
        } else {
            s = ((const int*)ei)[e];
            d = ((const int*)ei)[NE + e];
        }
        d_src[e] = s;
        d_dst[e] = d;
        atomicAdd(&d_degi[s], 1);
        atomicAdd(&d_cnt[d], 1);
    }
    if (e < NN) {
        d_batch[e] = is64 ? (int)((const long long*)batch)[e] : ((const int*)batch)[e];
    }
}

__global__ void dinv_kernel() {
    int i = blockIdx.x * blockDim.x + threadIdx.x;
    if (i < NN) {
        int dg = d_degi[i];
        d_dinv[i] = (dg > 0) ? rsqrtf((float)dg) : 0.0f;
    }
}

// ---------------- 3-pass exclusive scan ----------------
__global__ void scan1_kernel() {
    __shared__ int s[256];
    int tid = threadIdx.x;
    int i = blockIdx.x * 256 + tid;
    int v = (i < NN) ? d_cnt[i] : 0;
    s[tid] = v;
    __syncthreads();
    for (int off = 1; off < 256; off <<= 1) {
        int t = (tid >= off) ? s[tid - off] : 0;
        __syncthreads();
        s[tid] += t;
        __syncthreads();
    }
    int incl = s[tid];
    if (i < NN) d_rowptr[i] = incl - v;
    if (tid == 255) d_bsum[blockIdx.x] = incl;
}

__global__ void scan2_kernel() {
    __shared__ int s[256];
    int tid = threadIdx.x;
    int v = (tid < NCHUNK) ? d_bsum[tid] : 0;
    s[tid] = v;
    __syncthreads();
    for (int off = 1; off < 256; off <<= 1) {
        int t = (tid >= off) ? s[tid - off] : 0;
        __syncthreads();
        s[tid] += t;
        __syncthreads();
    }
    d_boff[tid] = s[tid] - v;
}

__global__ void scan3_kernel() {
    int i = blockIdx.x * blockDim.x + threadIdx.x;
    if (i < NN) {
        int r = d_rowptr[i] + d_boff[i >> 8];
        d_rowptr[i] = r;
        d_cursor[i] = r;
    }
    if (i == NN) d_rowptr[NN] = NE;
}

// ---------------- scatter + edge-weight compute ----------------
__global__ void scatter_kernel() {
    int e = blockIdx.x * blockDim.x + threadIdx.x;
    if (e < NE) {
        int s = d_src[e], d = d_dst[e];
        int p = atomicAdd(&d_cursor[d], 1);
        d_csr_src[p] = s;
        d_csr_w[p] = -(d_dinv[s] * d_dinv[d]);
    }
}

// ---------------- folded weights: Wa=W0-W2, Wb=W1, Wc=2*W2 -> bf16 hi/lo ----------------
__device__ __forceinline__ void emit_w(int idx, float v) {
    __nv_bfloat16 h = __float2bfloat16(v);
    d_Whi[idx] = h;
    d_Wlo[idx] = __float2bfloat16(v - __bfloat162float(h));
}
__global__ void wconv_kernel(const float* __restrict__ W1, const float* __restrict__ W2,
                             const float* __restrict__ W3) {
    int i = blockIdx.x * blockDim.x + threadIdx.x;
    if (i >= WTERM) return;
    const float* Ws[3] = {W1, W2, W3};
#pragma unroll
    for (int l = 0; l < 3; ++l) {
        float w0 = Ws[l][i];
        float w1 = Ws[l][WTERM + i];
        float w2 = Ws[l][2 * WTERM + i];
        int base = l * WSZ;
        emit_w(base + i, w0 - w2);
        emit_w(base + WTERM + i, w1);
        emit_w(base + 2 * WTERM + i, 2.0f * w2);
    }
}

// ---------------- x -> fp16 copy ----------------
__global__ void xconv_kernel(const float4* __restrict__ x) {
    int i = blockIdx.x * blockDim.x + threadIdx.x;
    if (i >= NN * 32) return;
    float4 v = x[i];
    __half2 a = __floats2half2_rn(v.x, v.y);
    __half2 b = __floats2half2_rn(v.z, v.w);
    uint2 p;
    p.x = *reinterpret_cast<uint32_t*>(&a);
    p.y = *reinterpret_cast<uint32_t*>(&b);
    d_h16a[i] = p;
}

// ---------------- lhat: gather fp16 rows, fp32 accumulate ----------------
template <bool W16>
__global__ void lhat_kernel(const uint2* __restrict__ in, float* __restrict__ out,
                            uint2* __restrict__ out16) {
    int w = (blockIdx.x * blockDim.x + threadIdx.x) >> 5;
    int lane = threadIdx.x & 31;
    if (w >= NN) return;
    int e = d_rowptr[w];
    const int e1 = d_rowptr[w + 1];
    float4 acc = make_float4(0.f, 0.f, 0.f, 0.f);
    for (; e + 4 <= e1; e += 4) {
#pragma unroll
        for (int j = 0; j < 4; ++j) {
            int s = d_csr_src[e + j];
            float wj = d_csr_w[e + j];
            uint2 p = in[(size_t)s * 32 + lane];
            float2 f0 = __half22float2(*reinterpret_cast<__half2*>(&p.x));
            float2 f1 = __half22float2(*reinterpret_cast<__half2*>(&p.y));
            acc.x += wj * f0.x; acc.y += wj * f0.y;
            acc.z += wj * f1.x; acc.w += wj * f1.y;
        }
    }
    for (; e < e1; ++e) {
        int s = d_csr_src[e];
        float wj = d_csr_w[e];
        uint2 p = in[(size_t)s * 32 + lane];
        float2 f0 = __half22float2(*reinterpret_cast<__half2*>(&p.x));
        float2 f1 = __half22float2(*reinterpret_cast<__half2*>(&p.y));
        acc.x += wj * f0.x; acc.y += wj * f0.y;
        acc.z += wj * f1.x; acc.w += wj * f1.y;
    }
    *(float4*)&out[(size_t)w * D + lane * 4] = acc;
    if (W16) {
        __half2 a = __floats2half2_rn(acc.x, acc.y);
        __half2 b = __floats2half2_rn(acc.z, acc.w);
        uint2 p;
        p.x = *reinterpret_cast<uint32_t*>(&a);
        p.y = *reinterpret_cast<uint32_t*>(&b);
        out16[(size_t)w * 32 + lane] = p;
    }
}

// ---------------- tensor-core gemm helpers ----------------
__device__ __forceinline__ void ldsm4(uint32_t a, uint32_t& r0, uint32_t& r1,
                                      uint32_t& r2, uint32_t& r3) {
    asm volatile("ldmatrix.sync.aligned.m8n8.x4.shared.b16 {%0,%1,%2,%3}, [%4];"
                 : "=r"(r0), "=r"(r1), "=r"(r2), "=r"(r3) : "r"(a));
}
__device__ __forceinline__ void ldsm4t(uint32_t a, uint32_t& r0, uint32_t& r1,
                                       uint32_t& r2, uint32_t& r3) {
    asm volatile("ldmatrix.sync.aligned.m8n8.x4.trans.shared.b16 {%0,%1,%2,%3}, [%4];"
                 : "=r"(r0), "=r"(r1), "=r"(r2), "=r"(r3) : "r"(a));
}
__device__ __forceinline__ void mma16816(float* c, const uint32_t* a, const uint32_t* b) {
    asm volatile(
        "mma.sync.aligned.m16n8k16.row.col.f32.bf16.bf16.f32 "
        "{%0,%1,%2,%3}, {%4,%5,%6,%7}, {%8,%9}, {%0,%1,%2,%3};"
        : "+f"(c[0]), "+f"(c[1]), "+f"(c[2]), "+f"(c[3])
        : "r"(a[0]), "r"(a[1]), "r"(a[2]), "r"(a[3]), "r"(b[0]), "r"(b[1]));
}
__device__ __forceinline__ uint32_t packbf(__nv_bfloat16 a, __nv_bfloat16 b) {
    return (uint32_t)__bfloat16_as_ushort(a) | ((uint32_t)__bfloat16_as_ushort(b) << 16);
}
__device__ __forceinline__ void cvt_hilo4(float4 v, uint2& hi, uint2& lo) {
    __nv_bfloat16 h0 = __float2bfloat16(v.x), h1 = __float2bfloat16(v.y);
    __nv_bfloat16 h2 = __float2bfloat16(v.z), h3 = __float2bfloat16(v.w);
    __nv_bfloat16 l0 = __float2bfloat16(v.x - __bfloat162float(h0));
    __nv_bfloat16 l1 = __float2bfloat16(v.y - __bfloat162float(h1));
    __nv_bfloat16 l2 = __float2bfloat16(v.z - __bfloat162float(h2));
    __nv_bfloat16 l3 = __float2bfloat16(v.w - __bfloat162float(h3));
    hi = make_uint2(packbf(h0, h1), packbf(h2, h3));
    lo = make_uint2(packbf(l0, l1), packbf(l2, l3));
}

// ---------------- Out = relu(X0@Wa + X1@Wb + X2@Wc + b); fp32 + fp16 outputs ----------------
__global__ void __launch_bounds__(256) gemm3_kernel(
    const float* __restrict__ X0, const float* __restrict__ X1,
    const float* __restrict__ X2, const __nv_bfloat16* __restrict__ Whi,
    const __nv_bfloat16* __restrict__ Wlo, const float* __restrict__ bias,
    float* __restrict__ Out, uint32_t* __restrict__ Outh)
{
    __shared__ __align__(16) unsigned char sA_hi[128 * 48];
    __shared__ __align__(16) unsigned char sA_lo[128 * 48];
    __shared__ __align__(16) unsigned char sB_hi[16 * 272];
    __shared__ __align__(16) unsigned char sB_lo[16 * 272];
    __shared__ float s_bias[128];

    const int tid = threadIdx.x;
    const int lane = tid & 31;
    const int wid = tid >> 5;
    const int wr = wid >> 2;
    const int wc = wid & 3;
    const int m0 = blockIdx.x * 128;

    if (tid < 128) s_bias[tid] = bias[tid];

    float acc[4][4][4];
#pragma unroll
    for (int f = 0; f < 4; ++f)
#pragma unroll
        for (int t = 0; t < 4; ++t)
#pragma unroll
            for (int i = 0; i < 4; ++i) acc[f][t][i] = 0.f;

    const uint32_t sAhiB = (uint32_t)__cvta_generic_to_shared(sA_hi);
    const uint32_t sAloB = (uint32_t)__cvta_generic_to_shared(sA_lo);
    const uint32_t sBhiB = (uint32_t)__cvta_generic_to_shared(sB_hi);
    const uint32_t sBloB = (uint32_t)__cvta_generic_to_shared(sB_lo);

    const uint32_t aoff = (uint32_t)(lane & 15) * 48 + (uint32_t)(lane >> 4) * 16;
    const uint32_t boff = (uint32_t)(lane & 15) * 272 + (uint32_t)((lane >> 4) * 8) * 2;

    for (int sel = 0; sel < 3; ++sel) {
        const float* X = (sel == 0) ? X0 : (sel == 1) ? X1 : X2;
        const __nv_bfloat16* WH = Whi + sel * (D * D);
        const __nv_bfloat16* WL = Wlo + sel * (D * D);
        for (int kb = 0; kb < 8; ++kb) {
            const int kc0 = kb * 16;
#pragma unroll
            for (int j = 0; j < 2; ++j) {
                int id = tid + j * 256;
                int row = id >> 2, cg = id & 3;
                int m = m0 + row;
                float4 v = make_float4(0.f, 0.f, 0.f, 0.f);
                if (m < NN) v = *(const float4*)&X[(size_t)m * D + kc0 + cg * 4];
                uint2 hi, lo;
                cvt_hilo4(v, hi, lo);
                *(uint2*)(sA_hi + row * 48 + cg * 8) = hi;
                *(uint2*)(sA_lo + row * 48 + cg * 8) = lo;
            }
            {
                int row = tid >> 4, c8 = (tid & 15) * 8;
                *(uint4*)(sB_hi + row * 272 + c8 * 2) =
                    *(const uint4*)(WH + (kc0 + row) * D + c8);
                *(uint4*)(sB_lo + row * 272 + c8 * 2) =
                    *(const uint4*)(WL + (kc0 + row) * D + c8);
            }
            __syncthreads();

            uint32_t ahi[4][4], alo[4][4], bhi[4][2], blo[4][2];
#pragma unroll
            for (int f = 0; f < 4; ++f) {
                uint32_t rb = (uint32_t)(wr * 64 + f * 16) * 48 + aoff;
                ldsm4(sAhiB + rb, ahi[f][0], ahi[f][1], ahi[f][2], ahi[f][3]);
                ldsm4(sAloB + rb, alo[f][0], alo[f][1], alo[f][2], alo[f][3]);
            }
#pragma unroll
            for (int nb = 0; nb < 2; ++nb) {
                uint32_t cb = boff + (uint32_t)(wc * 32 + nb * 16) * 2;
                uint32_t r0, r1, r2, r3;
                ldsm4t(sBhiB + cb, r0, r1, r2, r3);
                bhi[nb * 2][0] = r0; bhi[nb * 2][1] = r1;
                bhi[nb * 2 + 1][0] = r2; bhi[nb * 2 + 1][1] = r3;
                ldsm4t(sBloB + cb, r0, r1, r2, r3);
                blo[nb * 2][0] = r0; blo[nb * 2][1] = r1;
                blo[nb * 2 + 1][0] = r2; blo[nb * 2 + 1][1] = r3;
            }
#pragma unroll
            for (int f = 0; f < 4; ++f)
#pragma unroll
                for (int t = 0; t < 4; ++t) {
                    mma16816(acc[f][t], ahi[f], bhi[t]);
                    mma16816(acc[f][t], ahi[f], blo[t]);
                    mma16816(acc[f][t], alo[f], bhi[t]);
                }
            __syncthreads();
        }
    }

#pragma unroll
    for (int f = 0; f < 4; ++f) {
        int r0 = m0 + wr * 64 + f * 16 + (lane >> 2);
        int r1 = r0 + 8;
#pragma unroll
        for (int t = 0; t < 4; ++t) {
            int cb = wc * 32 + t * 8 + (lane & 3) * 2;
            if (r0 < NN) {
                float2 o;
                o.x = fmaxf(acc[f][t][0] + s_bias[cb], 0.f);
                o.y = fmaxf(acc[f][t][1] + s_bias[cb + 1], 0.f);
                *(float2*)&Out[(size_t)r0 * D + cb] = o;
                __half2 h = __floats2half2_rn(o.x, o.y);
                Outh[(size_t)r0 * 64 + (cb >> 1)] = *reinterpret_cast<uint32_t*>(&h);
            }
            if (r1 < NN) {
                float2 o;
                o.x = fmaxf(acc[f][t][2] + s_bias[cb], 0.f);
                o.y = fmaxf(acc[f][t][3] + s_bias[cb + 1], 0.f);
                *(float2*)&Out[(size_t)r1 * D + cb] = o;
                __half2 h = __floats2half2_rn(o.x, o.y);
                Outh[(size_t)r1 * 64 + (cb >> 1)] = *reinterpret_cast<uint32_t*>(&h);
            }
        }
    }
}

// ---------------- fused mean-pool + output projection ----------------
__global__ void poolfinal_kernel(const float* __restrict__ H, const float* __restrict__ Wout,
                                 const float* __restrict__ bout, float* __restrict__ out) {
    int g = blockIdx.x;
    int t = threadIdx.x;  // 128
    __shared__ float sp[128];
    // binary search graph boundaries in sorted batch
    int lo = 0, hi = NN;
    while (lo < hi) { int m = (lo + hi) >> 1; if (d_batch[m] < g) lo = m + 1; else hi = m; }
    int s = lo;
    lo = 0; hi = NN;
    while (lo < hi) { int m = (lo + hi) >> 1; if (d_batch[m] < g + 1) lo = m + 1; else hi = m; }
    int e = lo;
    float acc = 0.f;
    for (int n = s; n < e; ++n) acc += H[(size_t)n * D + t];
    sp[t] = acc / fmaxf((float)(e - s), 1.0f);
    __syncthreads();
    if (t < DOUT) {
        float a = 0.f;
#pragma unroll 8
        for (int i = 0; i < D; ++i) a += sp[i] * Wout[i * DOUT + t];
        out[g * DOUT + t] = bout[t] + a;
    }
}

// ---------------- launch ----------------
extern "C" void kernel_launch(void* const* d_in, const int* in_sizes, int n_in,
                              void* d_out, int out_size) {
    const float* x     = (const float*)d_in[0];
    const void*  ei    = d_in[1];
    const void*  batch = d_in[2];
    const float* W1    = (const float*)d_in[3];
    const float* b1    = (const float*)d_in[4];
    const float* W2    = (const float*)d_in[5];
    const float* b2    = (const float*)d_in[6];
    const float* W3    = (const float*)d_in[7];
    const float* b3    = (const float*)d_in[8];
    const float* Wout  = (const float*)d_in[9];
    const float* bout  = (const float*)d_in[10];
    float* out = (float*)d_out;

    float *B0, *B1, *B2;
    uint2 *Ha, *Hb;
    __nv_bfloat16 *Whi, *Wlo;
    cudaGetSymbolAddress((void**)&B0, d_buf0);
    cudaGetSymbolAddress((void**)&B1, d_buf1);
    cudaGetSymbolAddress((void**)&B2, d_buf2);
    cudaGetSymbolAddress((void**)&Ha, d_h16a);
    cudaGetSymbolAddress((void**)&Hb, d_h16b);
    cudaGetSymbolAddress((void**)&Whi, d_Whi);
    cudaGetSymbolAddress((void**)&Wlo, d_Wlo);

    const int T = 256;
    const int gE = (NE + T - 1) / T;
    const int gN = (NN + T - 1) / T;
    const int gW = (NN * 32 + T - 1) / T;
    const int gM = (NN + 127) / 128;

    zero_kernel<<<gN, T>>>((const int*)ei);
    convert_kernel<<<gE, T>>>(ei, batch);
    dinv_kernel<<<gN, T>>>();
    scan1_kernel<<<NCHUNK, 256>>>();
    scan2_kernel<<<1, 256>>>();
    scan3_kernel<<<gN, T>>>();
    scatter_kernel<<<gE, T>>>();
    wconv_kernel<<<(WTERM + T - 1) / T, T>>>(W1, W2, W3);
    xconv_kernel<<<gW, T>>>((const float4*)x);

    // Layer 1: X=x (fp16 in Ha), Tx1 -> B0 (+Hb), Z -> B1, out -> B1 (+Ha)
    lhat_kernel<true><<<gW, T>>>(Ha, B0, Hb);
    lhat_kernel<false><<<gW, T>>>(Hb, B1, nullptr);
    gemm3_kernel<<<gM, 256>>>(x, B0, B1, Whi, Wlo, b1, B1, (uint32_t*)Ha);

    // Layer 2
    lhat_kernel<true><<<gW, T>>>(Ha, B0, Hb);
    lhat_kernel<false><<<gW, T>>>(Hb, B2, nullptr);
    gemm3_kernel<<<gM, 256>>>(B1, B0, B2, Whi + WSZ, Wlo + WSZ, b2, B2, (uint32_t*)Ha);

    // Layer 3
    lhat_kernel<true><<<gW, T>>>(Ha, B0, Hb);
    lhat_kernel<false><<<gW, T>>>(Hb, B1, nullptr);
    gemm3_kernel<<<gM, 256>>>(B2, B0, B1, Whi + 2 * WSZ, Wlo + 2 * WSZ, b3, B1, (uint32_t*)Ha);

    // Fused pool + projection
    poolfinal_kernel<<<NG, 128>>>(B1, Wout, bout, out);
}

// round 4
// speedup vs baseline: 3.1514x; 1.4552x over previous
#include <cuda_runtime.h>
#include <cuda_bf16.h>
#include <cuda_fp16.h>
#include <cstdint>

#define NN 50000
#define NE 600000
#define NG 500
#define D 128
#define DOUT 32
#define NCHUNK 196       // ceil(NN/256)
#define WTERM 16384      // 128*128
#define WSZ (3*WTERM)    // per-layer folded terms

// ---------------- scratch ----------------
__device__ int   g_is64;
__device__ int   d_src[NE];
__device__ int   d_dst[NE];
__device__ int   d_degi[NN];
__device__ float d_dinv[NN];
__device__ int   d_cnt[NN];
__device__ int   d_rowptr[NN + 1];
__device__ int   d_cursor[NN];
__device__ int   d_bsum[256];
__device__ int   d_boff[256];
__device__ int   d_csr_src[NE];
__device__ float d_csr_w[NE];
__device__ int   d_batch[NN];
__device__ float d_bufH[(size_t)NN * D];    // final fp32 H for pooling
__device__ uint2 d_h16a[(size_t)NN * 32];   // fp16 X
__device__ uint2 d_h16b[(size_t)NN * 32];   // fp16 Tx1
__device__ uint2 d_h16c[(size_t)NN * 32];   // fp16 Tx2
__device__ __half d_W16[3 * WSZ];           // folded fp16 weights

// ---------------- zero + dtype detect ----------------
__global__ void zero_kernel(const int* __restrict__ ei_raw) {
    int i = blockIdx.x * blockDim.x + threadIdx.x;
    if (i < NN) { d_degi[i] = 0; d_cnt[i] = 0; }
    if (blockIdx.x == 0 && threadIdx.x < 32) {
        int nz = 0;
        for (int j = threadIdx.x; j < 2048; j += 32)
            if (j & 1) nz += (ei_raw[j] != 0);
        for (int off = 16; off > 0; off >>= 1)
            nz += __shfl_down_sync(0xFFFFFFFFu, nz, off);
        if (threadIdx.x == 0) g_is64 = (nz == 0) ? 1 : 0;
    }
}

// ---------------- convert + both degree histograms ----------------
__global__ void convert_kernel(const void* __restrict__ ei, const void* __restrict__ batch) {
    int e = blockIdx.x * blockDim.x + threadIdx.x;
    const bool is64 = (g_is64 != 0);
    if (e < NE) {
        int s, d;
        if (is64) {
            s = (int)((const long long*)ei)[e];
            d = (int)((const long long*)ei)[(size_t)NE + e];
        } else {
            s = ((const int*)ei)[e];
            d = ((const int*)ei)[NE + e];
        }
        d_src[e] = s;
        d_dst[e] = d;
        atomicAdd(&d_degi[s], 1);
        atomicAdd(&d_cnt[d], 1);
    }
    if (e < NN) {
        d_batch[e] = is64 ? (int)((const long long*)batch)[e] : ((const int*)batch)[e];
    }
}

// ---------------- scan pass 1 (+ fused dinv) ----------------
__global__ void scan1_kernel() {
    __shared__ int s[256];
    int tid = threadIdx.x;
    int i = blockIdx.x * 256 + tid;
    if (i < NN) {
        int dg = d_degi[i];
        d_dinv[i] = (dg > 0) ? rsqrtf((float)dg) : 0.0f;
    }
    int v = (i < NN) ? d_cnt[i] : 0;
    s[tid] = v;
    __syncthreads();
    for (int off = 1; off < 256; off <<= 1) {
        int t = (tid >= off) ? s[tid - off] : 0;
        __syncthreads();
        s[tid] += t;
        __syncthreads();
    }
    int incl = s[tid];
    if (i < NN) d_rowptr[i] = incl - v;
    if (tid == 255) d_bsum[blockIdx.x] = incl;
}

__global__ void scan2_kernel() {
    __shared__ int s[256];
    int tid = threadIdx.x;
    int v = (tid < NCHUNK) ? d_bsum[tid] : 0;
    s[tid] = v;
    __syncthreads();
    for (int off = 1; off < 256; off <<= 1) {
        int t = (tid >= off) ? s[tid - off] : 0;
        __syncthreads();
        s[tid] += t;
        __syncthreads();
    }
    d_boff[tid] = s[tid] - v;
}

__global__ void scan3_kernel() {
    int i = blockIdx.x * blockDim.x + threadIdx.x;
    if (i < NN) {
        int r = d_rowptr[i] + d_boff[i >> 8];
        d_rowptr[i] = r;
        d_cursor[i] = r;
    }
    if (i == NN) d_rowptr[NN] = NE;
}

// ---------------- scatter + edge-weight compute ----------------
__global__ void scatter_kernel() {
    int e = blockIdx.x * blockDim.x + threadIdx.x;
    if (e < NE) {
        int s = d_src[e], d = d_dst[e];
        int p = atomicAdd(&d_cursor[d], 1);
        d_csr_src[p] = s;
        d_csr_w[p] = -(d_dinv[s] * d_dinv[d]);
    }
}

// ---------------- folded weights: Wa=W0-W2, Wb=W1, Wc=2*W2 -> fp16 ----------------
__global__ void wconv_kernel(const float* __restrict__ W1, const float* __restrict__ W2,
                             const float* __restrict__ W3) {
    int i = blockIdx.x * blockDim.x + threadIdx.x;
    if (i >= WTERM) return;
    const float* Ws[3] = {W1, W2, W3};
#pragma unroll
    for (int l = 0; l < 3; ++l) {
        float w0 = Ws[l][i];
        float w1 = Ws[l][WTERM + i];
        float w2 = Ws[l][2 * WTERM + i];
        int base = l * WSZ;
        d_W16[base + i] = __float2half_rn(w0 - w2);
        d_W16[base + WTERM + i] = __float2half_rn(w1);
        d_W16[base + 2 * WTERM + i] = __float2half_rn(2.0f * w2);
    }
}

// ---------------- x -> fp16 copy ----------------
__global__ void xconv_kernel(const float4* __restrict__ x) {
    int i = blockIdx.x * blockDim.x + threadIdx.x;
    if (i >= NN * 32) return;
    float4 v = x[i];
    __half2 a = __floats2half2_rn(v.x, v.y);
    __half2 b = __floats2half2_rn(v.z, v.w);
    uint2 p;
    p.x = *reinterpret_cast<uint32_t*>(&a);
    p.y = *reinterpret_cast<uint32_t*>(&b);
    d_h16a[i] = p;
}

// ---------------- lhat: fp16 gather, fp32 accumulate, fp16 out; unroll 8 ----------------
__global__ void lhat_kernel(const uint2* __restrict__ in, uint2* __restrict__ out16) {
    int w = (blockIdx.x * blockDim.x + threadIdx.x) >> 5;
    int lane = threadIdx.x & 31;
    if (w >= NN) return;
    int e = d_rowptr[w];
    const int e1 = d_rowptr[w + 1];
    float4 acc = make_float4(0.f, 0.f, 0.f, 0.f);
    for (; e + 8 <= e1; e += 8) {
        int   si[8];
        float wi[8];
        uint2 pi[8];
#pragma unroll
        for (int j = 0; j < 8; ++j) { si[j] = d_csr_src[e + j]; wi[j] = d_csr_w[e + j]; }
#pragma unroll
        for (int j = 0; j < 8; ++j) pi[j] = in[(size_t)si[j] * 32 + lane];
#pragma unroll
        for (int j = 0; j < 8; ++j) {
            float2 f0 = __half22float2(*reinterpret_cast<__half2*>(&pi[j].x));
            float2 f1 = __half22float2(*reinterpret_cast<__half2*>(&pi[j].y));
            acc.x += wi[j] * f0.x; acc.y += wi[j] * f0.y;
            acc.z += wi[j] * f1.x; acc.w += wi[j] * f1.y;
        }
    }
    {
        int rem = e1 - e;
        int   si[7];
        float wi[7];
        uint2 pi[7];
#pragma unroll
        for (int j = 0; j < 7; ++j)
            if (j < rem) { si[j] = d_csr_src[e + j]; wi[j] = d_csr_w[e + j]; }
#pragma unroll
        for (int j = 0; j < 7; ++j)
            if (j < rem) pi[j] = in[(size_t)si[j] * 32 + lane];
#pragma unroll
        for (int j = 0; j < 7; ++j)
            if (j < rem) {
                float2 f0 = __half22float2(*reinterpret_cast<__half2*>(&pi[j].x));
                float2 f1 = __half22float2(*reinterpret_cast<__half2*>(&pi[j].y));
                acc.x += wi[j] * f0.x; acc.y += wi[j] * f0.y;
                acc.z += wi[j] * f1.x; acc.w += wi[j] * f1.y;
            }
    }
    __half2 a = __floats2half2_rn(acc.x, acc.y);
    __half2 b = __floats2half2_rn(acc.z, acc.w);
    uint2 p;
    p.x = *reinterpret_cast<uint32_t*>(&a);
    p.y = *reinterpret_cast<uint32_t*>(&b);
    out16[(size_t)w * 32 + lane] = p;
}

// ---------------- tensor-core helpers ----------------
__device__ __forceinline__ void ldsm4(uint32_t a, uint32_t& r0, uint32_t& r1,
                                      uint32_t& r2, uint32_t& r3) {
    asm volatile("ldmatrix.sync.aligned.m8n8.x4.shared.b16 {%0,%1,%2,%3}, [%4];"
                 : "=r"(r0), "=r"(r1), "=r"(r2), "=r"(r3) : "r"(a));
}
__device__ __forceinline__ void ldsm4t(uint32_t a, uint32_t& r0, uint32_t& r1,
                                       uint32_t& r2, uint32_t& r3) {
    asm volatile("ldmatrix.sync.aligned.m8n8.x4.trans.shared.b16 {%0,%1,%2,%3}, [%4];"
                 : "=r"(r0), "=r"(r1), "=r"(r2), "=r"(r3) : "r"(a));
}
__device__ __forceinline__ void mma16816h(float* c, const uint32_t* a, const uint32_t* b) {
    asm volatile(
        "mma.sync.aligned.m16n8k16.row.col.f32.f16.f16.f32 "
        "{%0,%1,%2,%3}, {%4,%5,%6,%7}, {%8,%9}, {%0,%1,%2,%3};"
        : "+f"(c[0]), "+f"(c[1]), "+f"(c[2]), "+f"(c[3])
        : "r"(a[0]), "r"(a[1]), "r"(a[2]), "r"(a[3]), "r"(b[0]), "r"(b[1]));
}

// ---------------- Out = relu(X0@Wa + X1@Wb + X2@Wc + b); all-fp16 operands ----------------
template <bool LAST>
__global__ void __launch_bounds__(256) gemm3_kernel(
    const uint4* __restrict__ X0, const uint4* __restrict__ X1,
    const uint4* __restrict__ X2, const __half* __restrict__ W16,
    const float* __restrict__ bias, float* __restrict__ Out,
    uint32_t* __restrict__ Outh)
{
    __shared__ __align__(16) unsigned char sA[128 * 48];   // 128 rows x 16 fp16 (+pad)
    __shared__ __align__(16) unsigned char sB[16 * 272];   // 16 k x 128 fp16 (+pad)
    __shared__ float s_bias[128];

    const int tid = threadIdx.x;
    const int lane = tid & 31;
    const int wid = tid >> 5;
    const int wr = wid >> 2;
    const int wc = wid & 3;
    const int m0 = blockIdx.x * 128;

    if (tid < 128) s_bias[tid] = bias[tid];

    float acc[4][4][4];
#pragma unroll
    for (int f = 0; f < 4; ++f)
#pragma unroll
        for (int t = 0; t < 4; ++t)
#pragma unroll
            for (int i = 0; i < 4; ++i) acc[f][t][i] = 0.f;

    const uint32_t sAB = (uint32_t)__cvta_generic_to_shared(sA);
    const uint32_t sBB = (uint32_t)__cvta_generic_to_shared(sB);
    const uint32_t aoff = (uint32_t)(lane & 15) * 48 + (uint32_t)(lane >> 4) * 16;
    const uint32_t boff = (uint32_t)(lane & 15) * 272 + (uint32_t)((lane >> 4) * 8) * 2;

    const int arow = tid >> 1;      // 0..127
    const int ahalf = tid & 1;      // 16B half of 32B row chunk
    const int brow = tid >> 4;      // 0..15
    const int bc = tid & 15;        // 16B group

    for (int sel = 0; sel < 3; ++sel) {
        const uint4* X = (sel == 0) ? X0 : (sel == 1) ? X1 : X2;
        const uint4* W = (const uint4*)(W16 + sel * (D * D));
        for (int kb = 0; kb < 8; ++kb) {
            // stage A: 128 x 16 fp16 (node row = 256B = 16 uint4)
            {
                int m = m0 + arow;
                uint4 v = make_uint4(0u, 0u, 0u, 0u);
                if (m < NN) v = X[(size_t)m * 16 + kb * 2 + ahalf];
                *(uint4*)(sA + arow * 48 + ahalf * 16) = v;
            }
            // stage B: 16 x 128 fp16
            {
                *(uint4*)(sB + brow * 272 + bc * 16) = W[(size_t)(kb * 16 + brow) * 16 + bc];
            }
            __syncthreads();

            uint32_t a[4][4], b[4][2];
#pragma unroll
            for (int f = 0; f < 4; ++f) {
                uint32_t rb = (uint32_t)(wr * 64 + f * 16) * 48 + aoff;
                ldsm4(sAB + rb, a[f][0], a[f][1], a[f][2], a[f][3]);
            }
#pragma unroll
            for (int nb = 0; nb < 2; ++nb) {
                uint32_t cb = boff + (uint32_t)(wc * 32 + nb * 16) * 2;
                uint32_t r0, r1, r2, r3;
                ldsm4t(sBB + cb, r0, r1, r2, r3);
                b[nb * 2][0] = r0; b[nb * 2][1] = r1;
                b[nb * 2 + 1][0] = r2; b[nb * 2 + 1][1] = r3;
            }
#pragma unroll
            for (int f = 0; f < 4; ++f)
#pragma unroll
                for (int t = 0; t < 4; ++t)
                    mma16816h(acc[f][t], a[f], b[t]);
            __syncthreads();
        }
    }

#pragma unroll
    for (int f = 0; f < 4; ++f) {
        int r0 = m0 + wr * 64 + f * 16 + (lane >> 2);
        int r1 = r0 + 8;
#pragma unroll
        for (int t = 0; t < 4; ++t) {
            int cb = wc * 32 + t * 8 + (lane & 3) * 2;
            if (r0 < NN) {
                float ox = fmaxf(acc[f][t][0] + s_bias[cb], 0.f);
                float oy = fmaxf(acc[f][t][1] + s_bias[cb + 1], 0.f);
                if (LAST) *(float2*)&Out[(size_t)r0 * D + cb] = make_float2(ox, oy);
                __half2 h = __floats2half2_rn(ox, oy);
                Outh[(size_t)r0 * 64 + (cb >> 1)] = *reinterpret_cast<uint32_t*>(&h);
            }
            if (r1 < NN) {
                float ox = fmaxf(acc[f][t][2] + s_bias[cb], 0.f);
                float oy = fmaxf(acc[f][t][3] + s_bias[cb + 1], 0.f);
                if (LAST) *(float2*)&Out[(size_t)r1 * D + cb] = make_float2(ox, oy);
                __half2 h = __floats2half2_rn(ox, oy);
                Outh[(size_t)r1 * 64 + (cb >> 1)] = *reinterpret_cast<uint32_t*>(&h);
            }
        }
    }
}

// ---------------- fused mean-pool + output projection ----------------
__global__ void poolfinal_kernel(const float* __restrict__ H, const float* __restrict__ Wout,
                                 const float* __restrict__ bout, float* __restrict__ out) {
    int g = blockIdx.x;
    int t = threadIdx.x;  // 128
    __shared__ float sp[128];
    int lo = 0, hi = NN;
    while (lo < hi) { int m = (lo + hi) >> 1; if (d_batch[m] < g) lo = m + 1; else hi = m; }
    int s = lo;
    lo = 0; hi = NN;
    while (lo < hi) { int m = (lo + hi) >> 1; if (d_batch[m] < g + 1) lo = m + 1; else hi = m; }
    int e = lo;
    float acc = 0.f;
    for (int n = s; n < e; ++n) acc += H[(size_t)n * D + t];
    sp[t] = acc / fmaxf((float)(e - s), 1.0f);
    __syncthreads();
    if (t < DOUT) {
        float a = 0.f;
#pragma unroll 8
        for (int i = 0; i < D; ++i) a += sp[i] * Wout[i * DOUT + t];
        out[g * DOUT + t] = bout[t] + a;
    }
}

// ---------------- launch ----------------
extern "C" void kernel_launch(void* const* d_in, const int* in_sizes, int n_in,
                              void* d_out, int out_size) {
    const float* x     = (const float*)d_in[0];
    const void*  ei    = d_in[1];
    const void*  batch = d_in[2];
    const float* W1    = (const float*)d_in[3];
    const float* b1    = (const float*)d_in[4];
    const float* W2    = (const float*)d_in[5];
    const float* b2    = (const float*)d_in[6];
    const float* W3    = (const float*)d_in[7];
    const float* b3    = (const float*)d_in[8];
    const float* Wout  = (const float*)d_in[9];
    const float* bout  = (const float*)d_in[10];
    float* out = (float*)d_out;

    float *BH;
    uint2 *Ha, *Hb, *Hc;
    __half *W16;
    cudaGetSymbolAddress((void**)&BH, d_bufH);
    cudaGetSymbolAddress((void**)&Ha, d_h16a);
    cudaGetSymbolAddress((void**)&Hb, d_h16b);
    cudaGetSymbolAddress((void**)&Hc, d_h16c);
    cudaGetSymbolAddress((void**)&W16, d_W16);

    const int T = 256;
    const int gE = (NE + T - 1) / T;
    const int gN = (NN + T - 1) / T;
    const int gW = (NN * 32 + T - 1) / T;
    const int gM = (NN + 127) / 128;

    zero_kernel<<<gN, T>>>((const int*)ei);
    convert_kernel<<<gE, T>>>(ei, batch);
    scan1_kernel<<<NCHUNK, 256>>>();
    scan2_kernel<<<1, 256>>>();
    scan3_kernel<<<gN, T>>>();
    scatter_kernel<<<gE, T>>>();
    wconv_kernel<<<(WTERM + T - 1) / T, T>>>(W1, W2, W3);
    xconv_kernel<<<gW, T>>>((const float4*)x);

    // Layer 1
    lhat_kernel<<<gW, T>>>(Ha, Hb);
    lhat_kernel<<<gW, T>>>(Hb, Hc);
    gemm3_kernel<false><<<gM, 256>>>((const uint4*)Ha, (const uint4*)Hb, (const uint4*)Hc,
                                     W16, b1, BH, (uint32_t*)Ha);
    // Layer 2
    lhat_kernel<<<gW, T>>>(Ha, Hb);
    lhat_kernel<<<gW, T>>>(Hb, Hc);
    gemm3_kernel<false><<<gM, 256>>>((const uint4*)Ha, (const uint4*)Hb, (const uint4*)Hc,
                                     W16 + WSZ, b2, BH, (uint32_t*)Ha);
    // Layer 3
    lhat_kernel<<<gW, T>>>(Ha, Hb);
    lhat_kernel<<<gW, T>>>(Hb, Hc);
    gemm3_kernel<true><<<gM, 256>>>((const uint4*)Ha, (const uint4*)Hb, (const uint4*)Hc,
                                    W16 + 2 * WSZ, b3, BH, (uint32_t*)Ha);

    poolfinal_kernel<<<NG, 128>>>(BH, Wout, bout, out);
}